// round 9
// baseline (speedup 1.0000x reference)
#include <cuda_runtime.h>
#include <cuda_bf16.h>

// Two-kernel split.
// K1 (gather, barrier-free, ~roofline): spart[h][row][f], degp[h][row]
// K2 (epilogue GEMM, occupancy-fixed): out = relu((sp0+sp1)@W + bias*deg)

#define MJ   128
#define FE   64
#define FC   128
#define NROW 2048

__device__ float g_spart[2][NROW][FC];   // 2 MB scratch (static device: allowed)
__device__ float g_degp[2][NROW];

// ---------------------------------------------------------------------------
// Kernel 1: pure gather (unchanged from round 8 — measured ~70% of HBM spec).
// 256 thr = 8 warps = 4 rows/block, 2 warps per row, zero block barriers.
// ---------------------------------------------------------------------------
__global__ __launch_bounds__(256, 4)
void gcn_gather_kernel(const float* __restrict__ sf1,
                       const float* __restrict__ sf2,
                       const float* __restrict__ adj)
{
    __shared__ int   s_off[8][72];
    __shared__ float s_val[8][72];

    const int t    = threadIdx.x;
    const int w    = t >> 5;
    const int lane = t & 31;
    const int pr   = w >> 1;               // row within block
    const int h    = w & 1;                // j-half
    const int row  = blockIdx.x * 4 + pr;

    const float* arow = adj + (size_t)row * MJ + h * 64;
    const float a0 = __ldg(arow + lane);
    const float a1 = __ldg(arow + lane + 32);
    const unsigned b0 = __ballot_sync(0xffffffffu, a0 != 0.0f);
    const unsigned b1 = __ballot_sync(0xffffffffu, a1 != 0.0f);
    const int c0  = __popc(b0);
    const int nnz = c0 + __popc(b1);
    const unsigned lm = (1u << lane) - 1u;
    if (a0 != 0.0f) { const int p = __popc(b0 & lm);
                      s_off[w][p] = (h * 64 + lane     ) * FE; s_val[w][p] = a0; }
    if (a1 != 0.0f) { const int p = c0 + __popc(b1 & lm);
                      s_off[w][p] = (h * 64 + lane + 32) * FE; s_val[w][p] = a1; }
    if (lane < 8) {                        // pad: batches always full
        s_off[w][nnz + lane] = 0;
        s_val[w][nnz + lane] = 0.0f;
    }
    {
        float d = a0 + a1;
        #pragma unroll
        for (int off = 16; off > 0; off >>= 1)
            d += __shfl_down_sync(0xffffffffu, d, off);
        if (lane == 0) g_degp[h][row] = d;
    }
    __syncwarp();

    const float* base = ((lane < 16) ? sf1 : sf2)
                      + (size_t)row * MJ * FE + (lane & 15) * 4;
    float4 acc0 = make_float4(0.f, 0.f, 0.f, 0.f);
    float4 acc1 = make_float4(0.f, 0.f, 0.f, 0.f);
    for (int k = 0; k < nnz; k += 8) {
        const int o0 = s_off[w][k    ], o1 = s_off[w][k + 1];
        const int o2 = s_off[w][k + 2], o3 = s_off[w][k + 3];
        const int o4 = s_off[w][k + 4], o5 = s_off[w][k + 5];
        const int o6 = s_off[w][k + 6], o7 = s_off[w][k + 7];
        const float4 v0 = __ldcs(reinterpret_cast<const float4*>(base + o0));
        const float4 v1 = __ldcs(reinterpret_cast<const float4*>(base + o1));
        const float4 v2 = __ldcs(reinterpret_cast<const float4*>(base + o2));
        const float4 v3 = __ldcs(reinterpret_cast<const float4*>(base + o3));
        const float4 v4 = __ldcs(reinterpret_cast<const float4*>(base + o4));
        const float4 v5 = __ldcs(reinterpret_cast<const float4*>(base + o5));
        const float4 v6 = __ldcs(reinterpret_cast<const float4*>(base + o6));
        const float4 v7 = __ldcs(reinterpret_cast<const float4*>(base + o7));
        const float q0 = s_val[w][k    ], q1 = s_val[w][k + 1];
        const float q2 = s_val[w][k + 2], q3 = s_val[w][k + 3];
        const float q4 = s_val[w][k + 4], q5 = s_val[w][k + 5];
        const float q6 = s_val[w][k + 6], q7 = s_val[w][k + 7];
        acc0.x += q0 * v0.x; acc0.y += q0 * v0.y; acc0.z += q0 * v0.z; acc0.w += q0 * v0.w;
        acc1.x += q1 * v1.x; acc1.y += q1 * v1.y; acc1.z += q1 * v1.z; acc1.w += q1 * v1.w;
        acc0.x += q2 * v2.x; acc0.y += q2 * v2.y; acc0.z += q2 * v2.z; acc0.w += q2 * v2.w;
        acc1.x += q3 * v3.x; acc1.y += q3 * v3.y; acc1.z += q3 * v3.z; acc1.w += q3 * v3.w;
        acc0.x += q4 * v4.x; acc0.y += q4 * v4.y; acc0.z += q4 * v4.z; acc0.w += q4 * v4.w;
        acc1.x += q5 * v5.x; acc1.y += q5 * v5.y; acc1.z += q5 * v5.z; acc1.w += q5 * v5.w;
        acc0.x += q6 * v6.x; acc0.y += q6 * v6.y; acc0.z += q6 * v6.z; acc0.w += q6 * v6.w;
        acc1.x += q7 * v7.x; acc1.y += q7 * v7.y; acc1.z += q7 * v7.z; acc1.w += q7 * v7.w;
    }
    float4 s4;
    s4.x = acc0.x + acc1.x; s4.y = acc0.y + acc1.y;
    s4.z = acc0.z + acc1.z; s4.w = acc0.w + acc1.w;
    reinterpret_cast<float4*>(g_spart[h][row])[lane] = s4;
}

// ---------------------------------------------------------------------------
// Kernel 2: epilogue GEMM, rebuilt for occupancy.
// 4 rows/block -> grid 512. Warp = (row, K-half): thread owns a float4 of
// outputs, 64 fully-unrolled K-steps with 4 independent accumulators.
// 2-way split-K combined via one float4 smem handoff.
// ---------------------------------------------------------------------------
__global__ __launch_bounds__(256, 6)
void gcn_gemm_kernel(const float* __restrict__ W,
                     const float* __restrict__ bias,
                     float* __restrict__ out)
{
    __shared__ float  s_sm[4][FC];
    __shared__ float  s_deg[4];
    __shared__ float4 s_red[4][32];

    const int t    = threadIdx.x;
    const int w    = t >> 5;
    const int lane = t & 31;
    const int row0 = blockIdx.x * 4;

    // load + combine partial s vectors (4 rows x 32 quads = 128 threads)
    if (t < 128) {
        const int r = t >> 5, q = t & 31;
        const float4 p0 = reinterpret_cast<const float4*>(g_spart[0][row0 + r])[q];
        const float4 p1 = reinterpret_cast<const float4*>(g_spart[1][row0 + r])[q];
        float4 s;
        s.x = p0.x + p1.x; s.y = p0.y + p1.y;
        s.z = p0.z + p1.z; s.w = p0.w + p1.w;
        reinterpret_cast<float4*>(s_sm[r])[q] = s;
        if (q == 0) s_deg[r] = g_degp[0][row0 + r] + g_degp[1][row0 + r];
    }
    __syncthreads();

    // warp -> (row r, K-half h); thread -> output quad `lane`
    const int r = w >> 1;
    const int h = w & 1;
    const int k0 = h * 64;
    const float4* W4 = reinterpret_cast<const float4*>(W);

    float4 a0 = make_float4(0.f, 0.f, 0.f, 0.f);
    float4 a1 = make_float4(0.f, 0.f, 0.f, 0.f);
    float4 a2 = make_float4(0.f, 0.f, 0.f, 0.f);
    float4 a3 = make_float4(0.f, 0.f, 0.f, 0.f);
    #pragma unroll
    for (int kk = 0; kk < 64; kk += 4) {
        const float s0 = s_sm[r][k0 + kk    ];
        const float s1 = s_sm[r][k0 + kk + 1];
        const float s2 = s_sm[r][k0 + kk + 2];
        const float s3 = s_sm[r][k0 + kk + 3];
        const float4 w0 = W4[(k0 + kk    ) * 32 + lane];
        const float4 w1 = W4[(k0 + kk + 1) * 32 + lane];
        const float4 w2 = W4[(k0 + kk + 2) * 32 + lane];
        const float4 w3 = W4[(k0 + kk + 3) * 32 + lane];
        a0.x += s0 * w0.x; a0.y += s0 * w0.y; a0.z += s0 * w0.z; a0.w += s0 * w0.w;
        a1.x += s1 * w1.x; a1.y += s1 * w1.y; a1.z += s1 * w1.z; a1.w += s1 * w1.w;
        a2.x += s2 * w2.x; a2.y += s2 * w2.y; a2.z += s2 * w2.z; a2.w += s2 * w2.w;
        a3.x += s3 * w3.x; a3.y += s3 * w3.y; a3.z += s3 * w3.z; a3.w += s3 * w3.w;
    }
    float4 acc;
    acc.x = (a0.x + a1.x) + (a2.x + a3.x);
    acc.y = (a0.y + a1.y) + (a2.y + a3.y);
    acc.z = (a0.z + a1.z) + (a2.z + a3.z);
    acc.w = (a0.w + a1.w) + (a2.w + a3.w);

    if (h == 1) s_red[r][lane] = acc;
    __syncthreads();
    if (h == 0) {
        const float4 p = s_red[r][lane];
        const float4 bb = reinterpret_cast<const float4*>(bias)[lane];
        const float  d  = s_deg[r];
        float4 o4;
        o4.x = fmaxf(acc.x + p.x + bb.x * d, 0.0f);
        o4.y = fmaxf(acc.y + p.y + bb.y * d, 0.0f);
        o4.z = fmaxf(acc.z + p.z + bb.z * d, 0.0f);
        o4.w = fmaxf(acc.w + p.w + bb.w * d, 0.0f);
        reinterpret_cast<float4*>(out)[(size_t)(row0 + r) * 32 + lane] = o4;
    }
}

extern "C" void kernel_launch(void* const* d_in, const int* in_sizes, int n_in,
                              void* d_out, int out_size)
{
    const float* sf1  = (const float*)d_in[0];  // (16,128,128,64)
    const float* sf2  = (const float*)d_in[1];  // (16,128,128,64)
    const float* adj  = (const float*)d_in[2];  // (16,128,128)
    const float* W    = (const float*)d_in[3];  // (128,128)
    const float* bias = (const float*)d_in[4];  // (128,)
    float* out = (float*)d_out;                 // (16,128,128)

    gcn_gather_kernel<<<NROW / 4, 256>>>(sf1, sf2, adj);
    gcn_gemm_kernel<<<NROW / 4, 256>>>(W, bias, out);
}

// round 10
// speedup vs baseline: 1.2435x; 1.2435x over previous
#include <cuda_runtime.h>
#include <cuda_bf16.h>

// Fused, with INDEPENDENT 2-row groups inside each block.
// Block: 256 thr = 8 warps = 2 groups x 4 warps. Group owns 2 rows:
//   gather: warp (lr, h) compacts+gathers the h-th j-half of local row lr
//   bar.sync(1+g,128)
//   GEMM: warp q takes k-quarter, 2-row register blocking, combine halves
//         on the fly
//   bar.sync(1+g,128)
//   store
// Groups never wait on each other -> one group's GEMM FFMAs issue while the
// other group's gather loads are in flight (and across the ~3.5 blocks/SM).

#define MJ   128
#define FE   64
#define FC   128
#define NROW 2048

__global__ __launch_bounds__(256, 4)
void gcn_fused_kernel(const float* __restrict__ sf1,
                      const float* __restrict__ sf2,
                      const float* __restrict__ adj,
                      const float* __restrict__ W,
                      const float* __restrict__ bias,
                      float* __restrict__ out)
{
    __shared__ int    s_off[8][72];          // compacted j*FE offsets (+pad)
    __shared__ float  s_val[8][72];          // compacted adjacency values
    __shared__ float  s_part[8][FC];         // per-(row,half) partial s
    __shared__ float  s_degp[8];             // per-(row,half) partial degree
    __shared__ float4 s_red[2][4][2][32];    // [group][kq][row][quad]

    const int t    = threadIdx.x;
    const int w    = t >> 5;
    const int lane = t & 31;
    const int g    = w >> 2;                 // group 0/1
    const int lr   = w >> 1;                 // local row 0..3
    const int h    = w & 1;                  // j-half
    const int row0 = blockIdx.x * 4;
    const int row  = row0 + lr;

    // ---- gather phase (warp-local compaction, R7-proven) ----
    const float* arow = adj + (size_t)row * MJ + h * 64;
    const float a0 = __ldg(arow + lane);
    const float a1 = __ldg(arow + lane + 32);
    const unsigned b0 = __ballot_sync(0xffffffffu, a0 != 0.0f);
    const unsigned b1 = __ballot_sync(0xffffffffu, a1 != 0.0f);
    const int c0  = __popc(b0);
    const int nnz = c0 + __popc(b1);
    const unsigned lm = (1u << lane) - 1u;
    if (a0 != 0.0f) { const int p = __popc(b0 & lm);
                      s_off[w][p] = (h * 64 + lane     ) * FE; s_val[w][p] = a0; }
    if (a1 != 0.0f) { const int p = c0 + __popc(b1 & lm);
                      s_off[w][p] = (h * 64 + lane + 32) * FE; s_val[w][p] = a1; }
    if (lane < 8) {                          // zero-pad: batches always full
        s_off[w][nnz + lane] = 0;
        s_val[w][nnz + lane] = 0.0f;
    }
    {
        float d = a0 + a1;
        #pragma unroll
        for (int off = 16; off > 0; off >>= 1)
            d += __shfl_down_sync(0xffffffffu, d, off);
        if (lane == 0) s_degp[w] = d;
    }
    __syncwarp();

    {   // lanes 0-15: sf1 (ch 0..63); lanes 16-31: sf2 (ch 64..127)
        const float* base = ((lane < 16) ? sf1 : sf2)
                          + (size_t)row * MJ * FE + (lane & 15) * 4;
        float4 acc0 = make_float4(0.f, 0.f, 0.f, 0.f);
        float4 acc1 = make_float4(0.f, 0.f, 0.f, 0.f);
        for (int k = 0; k < nnz; k += 8) {   // padded: batch always valid
            const int o0 = s_off[w][k    ], o1 = s_off[w][k + 1];
            const int o2 = s_off[w][k + 2], o3 = s_off[w][k + 3];
            const int o4 = s_off[w][k + 4], o5 = s_off[w][k + 5];
            const int o6 = s_off[w][k + 6], o7 = s_off[w][k + 7];
            const float4 v0 = __ldcs(reinterpret_cast<const float4*>(base + o0));
            const float4 v1 = __ldcs(reinterpret_cast<const float4*>(base + o1));
            const float4 v2 = __ldcs(reinterpret_cast<const float4*>(base + o2));
            const float4 v3 = __ldcs(reinterpret_cast<const float4*>(base + o3));
            const float4 v4 = __ldcs(reinterpret_cast<const float4*>(base + o4));
            const float4 v5 = __ldcs(reinterpret_cast<const float4*>(base + o5));
            const float4 v6 = __ldcs(reinterpret_cast<const float4*>(base + o6));
            const float4 v7 = __ldcs(reinterpret_cast<const float4*>(base + o7));
            const float q0 = s_val[w][k    ], q1 = s_val[w][k + 1];
            const float q2 = s_val[w][k + 2], q3 = s_val[w][k + 3];
            const float q4 = s_val[w][k + 4], q5 = s_val[w][k + 5];
            const float q6 = s_val[w][k + 6], q7 = s_val[w][k + 7];
            acc0.x += q0 * v0.x; acc0.y += q0 * v0.y; acc0.z += q0 * v0.z; acc0.w += q0 * v0.w;
            acc1.x += q1 * v1.x; acc1.y += q1 * v1.y; acc1.z += q1 * v1.z; acc1.w += q1 * v1.w;
            acc0.x += q2 * v2.x; acc0.y += q2 * v2.y; acc0.z += q2 * v2.z; acc0.w += q2 * v2.w;
            acc1.x += q3 * v3.x; acc1.y += q3 * v3.y; acc1.z += q3 * v3.z; acc1.w += q3 * v3.w;
            acc0.x += q4 * v4.x; acc0.y += q4 * v4.y; acc0.z += q4 * v4.z; acc0.w += q4 * v4.w;
            acc1.x += q5 * v5.x; acc1.y += q5 * v5.y; acc1.z += q5 * v5.z; acc1.w += q5 * v5.w;
            acc0.x += q6 * v6.x; acc0.y += q6 * v6.y; acc0.z += q6 * v6.z; acc0.w += q6 * v6.w;
            acc1.x += q7 * v7.x; acc1.y += q7 * v7.y; acc1.z += q7 * v7.z; acc1.w += q7 * v7.w;
        }
        float4 s4;
        s4.x = acc0.x + acc1.x; s4.y = acc0.y + acc1.y;
        s4.z = acc0.z + acc1.z; s4.w = acc0.w + acc1.w;
        reinterpret_cast<float4*>(s_part[w])[lane] = s4;
    }

    // ---- group barrier #1 (only this group's 128 threads) ----
    asm volatile("bar.sync %0, %1;" :: "r"(1 + g), "r"(128) : "memory");

    // ---- GEMM: warp q = w&3 takes k-quarter; 2-row register blocking ----
    // rows of this group: lrA = 2g, lrB = 2g+1 (s halves at s_part[2*lr+h])
    {
        const int kq  = w & 3;
        const int f0  = kq * 32;
        const int iA0 = 4 * g;               // 2*lrA
        const int iB0 = 4 * g + 2;           // 2*lrB
        const float4* W4 = reinterpret_cast<const float4*>(W);
        float4 aA = make_float4(0.f, 0.f, 0.f, 0.f);
        float4 aB = make_float4(0.f, 0.f, 0.f, 0.f);
        #pragma unroll
        for (int kk = 0; kk < 32; ++kk) {
            const int f = f0 + kk;
            const float sA = s_part[iA0][f] + s_part[iA0 + 1][f];
            const float sB = s_part[iB0][f] + s_part[iB0 + 1][f];
            const float4 wv = __ldg(&W4[f * 32 + lane]);   // L1-resident
            aA.x += sA * wv.x; aA.y += sA * wv.y; aA.z += sA * wv.z; aA.w += sA * wv.w;
            aB.x += sB * wv.x; aB.y += sB * wv.y; aB.z += sB * wv.z; aB.w += sB * wv.w;
        }
        s_red[g][kq][0][lane] = aA;
        s_red[g][kq][1][lane] = aB;
    }

    // ---- group barrier #2 ----
    asm volatile("bar.sync %0, %1;" :: "r"(1 + g), "r"(128) : "memory");

    // ---- combine 4 k-quarters + bias*deg + relu + store (64 thr/group) ----
    {
        const int tg = t & 127;              // thread index within group
        if (tg < 64) {
            const int r  = tg >> 5;          // row within group (0/1)
            const int qd = tg & 31;          // output quad
            float4 rs = s_red[g][0][r][qd];
            #pragma unroll
            for (int sl = 1; sl < 4; ++sl) {
                const float4 p = s_red[g][sl][r][qd];
                rs.x += p.x; rs.y += p.y; rs.z += p.z; rs.w += p.w;
            }
            const int lrow = 2 * g + r;
            const float d  = s_degp[2 * lrow] + s_degp[2 * lrow + 1];
            const float4 bb = __ldg(&reinterpret_cast<const float4*>(bias)[qd]);
            float4 o4;
            o4.x = fmaxf(rs.x + bb.x * d, 0.0f);
            o4.y = fmaxf(rs.y + bb.y * d, 0.0f);
            o4.z = fmaxf(rs.z + bb.z * d, 0.0f);
            o4.w = fmaxf(rs.w + bb.w * d, 0.0f);
            reinterpret_cast<float4*>(out)[(size_t)(row0 + lrow) * 32 + qd] = o4;
        }
    }
}

extern "C" void kernel_launch(void* const* d_in, const int* in_sizes, int n_in,
                              void* d_out, int out_size)
{
    const float* sf1  = (const float*)d_in[0];  // (16,128,128,64)
    const float* sf2  = (const float*)d_in[1];  // (16,128,128,64)
    const float* adj  = (const float*)d_in[2];  // (16,128,128)
    const float* W    = (const float*)d_in[3];  // (128,128)
    const float* bias = (const float*)d_in[4];  // (128,)
    float* out = (float*)d_out;                 // (16,128,128)

    gcn_fused_kernel<<<NROW / 4, 256>>>(sf1, sf2, adj, W, bias, out);
}